// round 3
// baseline (speedup 1.0000x reference)
#include <cuda_runtime.h>
#include <cuda_bf16.h>

// Problem constants (match reference)
#define NN 100000
#define EE 1000000
#define HH 64
#define GG 512
#define CC 2

// Scratch (no allocation allowed -> __device__ globals)
__device__ __nv_bfloat16 g_xwh[NN * HH];  // X @ W for current layer (bf16, gather-optimized)
__device__ float g_h[NN * HH];            // hidden state / aggregation target (fp32)
__device__ float g_deg[NN];
__device__ float g_dinv[NN];
__device__ float g_selfc[NN];             // 2 * dinv^2
__device__ float g_norm[EE];
__device__ float g_pooled[GG * HH];
__device__ float g_cnt[GG];

// ---------------------------------------------------------------------------
// Zero the per-call accumulators (deg, pooled, cnt)
// ---------------------------------------------------------------------------
__global__ void init_kernel(int n_nodes) {
    int t = blockIdx.x * blockDim.x + threadIdx.x;
    if (t < n_nodes) g_deg[t] = 0.0f;
    if (t < GG * HH) g_pooled[t] = 0.0f;
    if (t < GG) g_cnt[t] = 0.0f;
}

// ---------------------------------------------------------------------------
// deg[dst] += w  (edge parallel)
// ---------------------------------------------------------------------------
__global__ void deg_kernel(const int* __restrict__ dst, const float* __restrict__ w, int E) {
    int e = blockIdx.x * blockDim.x + threadIdx.x;
    if (e < E) atomicAdd(&g_deg[dst[e]], w[e]);
}

// dinv = rsqrt(deg + 2); selfc = 2 * dinv^2
__global__ void dinv_kernel(int n_nodes) {
    int i = blockIdx.x * blockDim.x + threadIdx.x;
    if (i < n_nodes) {
        float d = g_deg[i] + 2.0f;
        float di = rsqrtf(d);
        g_dinv[i] = di;
        g_selfc[i] = 2.0f * di * di;
    }
}

// norm[e] = dinv[src] * w * dinv[dst]
__global__ void norm_kernel(const int* __restrict__ src, const int* __restrict__ dst,
                            const float* __restrict__ w, int E) {
    int e = blockIdx.x * blockDim.x + threadIdx.x;
    if (e < E) g_norm[e] = g_dinv[src[e]] * w[e] * g_dinv[dst[e]];
}

// ---------------------------------------------------------------------------
// GEMM: g_xwh = bf16(act(in) @ W) ; g_h = b + selfc * xw (fp32, self+bias fused)
// in == nullptr means "read g_h" (layers 2,3). In-place safe: each block reads
// its 128 rows to SMEM before writing them.
// Block: 256 threads, 128 rows. Thread tile: 16 rows x 2 adjacent cols.
// ---------------------------------------------------------------------------
__global__ __launch_bounds__(256) void gemm_kernel(
    const float* in, const float* __restrict__ W, const float* __restrict__ b,
    int n_rows, int relu_in)
{
    __shared__ float Ws[HH * HH];       // [k][c]
    __shared__ float Hs[128][HH];       // [r][k]

    const float* src_in = (in == nullptr) ? g_h : in;

    int tid = threadIdx.x;
    int row0 = blockIdx.x * 128;

    for (int i = tid; i < HH * HH; i += 256) Ws[i] = W[i];

    for (int i = tid; i < 128 * 16; i += 256) {
        int r = i >> 4;
        int c4 = i & 15;
        int grow = row0 + r;
        float4 v = make_float4(0.f, 0.f, 0.f, 0.f);
        if (grow < n_rows) v = ((const float4*)src_in)[grow * 16 + c4];
        if (relu_in) {
            v.x = fmaxf(v.x, 0.f); v.y = fmaxf(v.y, 0.f);
            v.z = fmaxf(v.z, 0.f); v.w = fmaxf(v.w, 0.f);
        }
        Hs[r][c4 * 4 + 0] = v.x;
        Hs[r][c4 * 4 + 1] = v.y;
        Hs[r][c4 * 4 + 2] = v.z;
        Hs[r][c4 * 4 + 3] = v.w;
    }
    __syncthreads();

    int tx = tid & 31;            // owns cols 2*tx, 2*tx+1
    int ty = tid >> 5;            // row group (16 rows each)
    int rbase = ty * 16;

    float acc0[16];
    float acc1[16];
    #pragma unroll
    for (int r = 0; r < 16; r++) { acc0[r] = 0.f; acc1[r] = 0.f; }

    #pragma unroll 8
    for (int k = 0; k < HH; k++) {
        float2 w = ((const float2*)Ws)[k * 32 + tx];
        #pragma unroll
        for (int r = 0; r < 16; r++) {
            float hv = Hs[rbase + r][k];   // warp-uniform -> smem broadcast
            acc0[r] += hv * w.x;
            acc1[r] += hv * w.y;
        }
    }

    float2 bv = ((const float2*)b)[tx];
    #pragma unroll
    for (int r = 0; r < 16; r++) {
        int grow = row0 + rbase + r;
        if (grow < n_rows) {
            float sc = g_selfc[grow];
            ((__nv_bfloat162*)g_xwh)[grow * 32 + tx] =
                __floats2bfloat162_rn(acc0[r], acc1[r]);
            float2 hv;
            hv.x = bv.x + sc * acc0[r];
            hv.y = bv.y + sc * acc1[r];
            ((float2*)g_h)[grow * 32 + tx] = hv;
        }
    }
}

// ---------------------------------------------------------------------------
// Scatter: g_h[dst] += norm[e] * fp32(g_xwh[src]). 8 lanes/edge; each lane
// gathers 16B (8 bf16) and issues two red.v4.f32. Gather = one 128B line/edge.
// ---------------------------------------------------------------------------
__global__ __launch_bounds__(256) void scatter_kernel(
    const int* __restrict__ src, const int* __restrict__ dst, int E)
{
    int t = blockIdx.x * blockDim.x + threadIdx.x;
    int e = t >> 3;
    if (e >= E) return;
    int lane = t & 7;
    int s = src[e];
    int d = dst[e];
    float nm = g_norm[e];

    uint4 raw = ((const uint4*)g_xwh)[s * 8 + lane];   // 8 bf16 = 16B

    float2 f0 = __bfloat1622float2(*(__nv_bfloat162*)&raw.x);
    float2 f1 = __bfloat1622float2(*(__nv_bfloat162*)&raw.y);
    float2 f2 = __bfloat1622float2(*(__nv_bfloat162*)&raw.z);
    float2 f3 = __bfloat1622float2(*(__nv_bfloat162*)&raw.w);

    float* p = g_h + d * HH + lane * 8;
    asm volatile("red.global.add.v4.f32 [%0], {%1, %2, %3, %4};"
                 :: "l"(p), "f"(f0.x * nm), "f"(f0.y * nm),
                    "f"(f1.x * nm), "f"(f1.y * nm) : "memory");
    asm volatile("red.global.add.v4.f32 [%0], {%1, %2, %3, %4};"
                 :: "l"(p + 4), "f"(f2.x * nm), "f"(f2.y * nm),
                    "f"(f3.x * nm), "f"(f3.y * nm) : "memory");
}

// ---------------------------------------------------------------------------
// Pool: pooled[batch[i]] += g_h[i]; cnt[batch[i]] += 1
// ---------------------------------------------------------------------------
__global__ __launch_bounds__(256) void pool_kernel(
    const int* __restrict__ batch, int n_nodes)
{
    int t = blockIdx.x * blockDim.x + threadIdx.x;
    int i = t >> 4;
    if (i >= n_nodes) return;
    int lane = t & 15;
    int g = batch[i];
    float4 v = ((const float4*)g_h)[i * 16 + lane];
    float* p = g_pooled + g * HH + lane * 4;
    asm volatile("red.global.add.v4.f32 [%0], {%1, %2, %3, %4};"
                 :: "l"(p), "f"(v.x), "f"(v.y), "f"(v.z), "f"(v.w) : "memory");
    if (lane == 0) atomicAdd(&g_cnt[g], 1.0f);
}

// ---------------------------------------------------------------------------
// Head: out[g][c] = (pooled[g]/cnt[g]) @ Wl + bl
// ---------------------------------------------------------------------------
__global__ void final_kernel(const float* __restrict__ Wl, const float* __restrict__ bl,
                             float* __restrict__ out)
{
    int t = blockIdx.x * blockDim.x + threadIdx.x;
    if (t >= GG * CC) return;
    int g = t >> 1;
    int c = t & 1;
    float inv = 1.0f / fmaxf(g_cnt[g], 1.0f);
    float s = 0.0f;
    #pragma unroll
    for (int k = 0; k < HH; k++) s += g_pooled[g * HH + k] * Wl[k * CC + c];
    out[t] = s * inv + bl[c];
}

// ---------------------------------------------------------------------------
extern "C" void kernel_launch(void* const* d_in, const int* in_sizes, int n_in,
                              void* d_out, int out_size)
{
    const float* x     = (const float*)d_in[0];
    const int*   ei    = (const int*)d_in[1];     // [2, E] row-major: src then dst
    const float* eattr = (const float*)d_in[2];
    const int*   batch = (const int*)d_in[3];
    const float* W1 = (const float*)d_in[4];
    const float* b1 = (const float*)d_in[5];
    const float* W2 = (const float*)d_in[6];
    const float* b2 = (const float*)d_in[7];
    const float* W3 = (const float*)d_in[8];
    const float* b3 = (const float*)d_in[9];
    const float* Wl = (const float*)d_in[10];
    const float* bl = (const float*)d_in[11];
    float* out = (float*)d_out;

    int N = in_sizes[0] / HH;
    int E = in_sizes[2];
    const int* src = ei;
    const int* dst = ei + E;

    int nb256 = (N + 255) / 256;
    int eb256 = (E + 255) / 256;
    int gemm_blocks = (N + 127) / 128;
    int scat_blocks = (E * 8 + 255) / 256;
    int pool_blocks = (N * 16 + 255) / 256;

    // Precompute (identical across layers: edge weights are layer-invariant)
    init_kernel<<<nb256, 256>>>(N);
    deg_kernel<<<eb256, 256>>>(dst, eattr, E);
    dinv_kernel<<<nb256, 256>>>(N);
    norm_kernel<<<eb256, 256>>>(src, dst, eattr, E);

    // Layer 1 (input x, no relu on input)
    gemm_kernel<<<gemm_blocks, 256>>>(x, W1, b1, N, 0);
    scatter_kernel<<<scat_blocks, 256>>>(src, dst, E);

    // Layer 2 (input g_h, relu fused into tile load)
    gemm_kernel<<<gemm_blocks, 256>>>(nullptr, W2, b2, N, 1);
    scatter_kernel<<<scat_blocks, 256>>>(src, dst, E);

    // Layer 3
    gemm_kernel<<<gemm_blocks, 256>>>(nullptr, W3, b3, N, 1);
    scatter_kernel<<<scat_blocks, 256>>>(src, dst, E);

    // Pool + head
    pool_kernel<<<pool_blocks, 256>>>(batch, N);
    final_kernel<<<(GG * CC + 255) / 256, 256>>>(Wl, bl, out);
}

// round 5
// speedup vs baseline: 1.2365x; 1.2365x over previous
#include <cuda_runtime.h>

// Problem constants (match reference)
#define NN 100000
#define EE 1000000
#define HH 64
#define GG 512
#define CC 2

// Scratch (no allocation allowed -> __device__ globals)
__device__ float g_xw[NN * HH];        // X @ W for current layer (fp32)
__device__ float g_h[NN * HH];         // hidden state (fp32)
__device__ float g_degw[NN];           // weighted degree
__device__ float g_dinv[NN];
__device__ float g_selfc[NN];          // 2 * dinv^2
__device__ int   g_hist[NN];           // unweighted in-degree (CSR sizes)
__device__ int   g_fill[NN];           // CSR fill cursors
__device__ int   g_rowptr[NN + 1];     // CSR row pointers
__device__ int   g_bsum[1024];         // block sums for scan
__device__ int   g_boff[1024];         // block offsets for scan
__device__ int2  g_epack[EE];          // per-edge {src, norm(bits)} sorted by dst
__device__ float g_pooled[GG * HH];
__device__ float g_cnt[GG];

// ---------------------------------------------------------------------------
// Zero per-call accumulators
// ---------------------------------------------------------------------------
__global__ void init_kernel(int n) {
    int t = blockIdx.x * blockDim.x + threadIdx.x;
    if (t < n) { g_degw[t] = 0.0f; g_hist[t] = 0; g_fill[t] = 0; }
    if (t < GG * HH) g_pooled[t] = 0.0f;
    if (t < GG) g_cnt[t] = 0.0f;
}

// deg[dst] += w ; hist[dst] += 1
__global__ void histdeg_kernel(const int* __restrict__ dst, const float* __restrict__ w, int E) {
    int e = blockIdx.x * blockDim.x + threadIdx.x;
    if (e < E) {
        int d = dst[e];
        atomicAdd(&g_degw[d], w[e]);
        atomicAdd(&g_hist[d], 1);
    }
}

// dinv = rsqrt(degw + 2); selfc = 2 * dinv^2
__global__ void dinv_kernel(int n) {
    int i = blockIdx.x * blockDim.x + threadIdx.x;
    if (i < n) {
        float di = rsqrtf(g_degw[i] + 2.0f);
        g_dinv[i] = di;
        g_selfc[i] = 2.0f * di * di;
    }
}

// ---------------------------------------------------------------------------
// 3-phase exclusive prefix scan of g_hist[0..n) -> g_rowptr
// ---------------------------------------------------------------------------
__global__ void scan_phase1(int n) {            // per-block sums
    __shared__ int s[256];
    int i = blockIdx.x * 256 + threadIdx.x;
    s[threadIdx.x] = (i < n) ? g_hist[i] : 0;
    __syncthreads();
    for (int off = 128; off > 0; off >>= 1) {
        if (threadIdx.x < off) s[threadIdx.x] += s[threadIdx.x + off];
        __syncthreads();
    }
    if (threadIdx.x == 0) g_bsum[blockIdx.x] = s[0];
}

__global__ void scan_phase2(int nblocks, int n, int E) {  // scan of block sums (1 block, 512 thr)
    __shared__ int s[512];
    int t = threadIdx.x;
    int v = (t < nblocks) ? g_bsum[t] : 0;
    s[t] = v;
    __syncthreads();
    for (int off = 1; off < 512; off <<= 1) {
        int add = (t >= off) ? s[t - off] : 0;
        __syncthreads();
        s[t] += add;
        __syncthreads();
    }
    if (t < nblocks) g_boff[t] = s[t] - v;     // exclusive
    if (t == 0) g_rowptr[n] = E;
}

__global__ void scan_phase3(int n) {            // local scan + offset
    __shared__ int s[256];
    int t = threadIdx.x;
    int i = blockIdx.x * 256 + t;
    int v = (i < n) ? g_hist[i] : 0;
    s[t] = v;
    __syncthreads();
    for (int off = 1; off < 256; off <<= 1) {
        int add = (t >= off) ? s[t - off] : 0;
        __syncthreads();
        s[t] += add;
        __syncthreads();
    }
    if (i < n) g_rowptr[i] = g_boff[blockIdx.x] + s[t] - v;  // exclusive
}

// ---------------------------------------------------------------------------
// CSR fill: slot = rowptr[dst] + fill[dst]++; epack[slot] = {src, norm}
// norm computed inline: dinv[src] * w * dinv[dst]
// ---------------------------------------------------------------------------
__global__ void fill_kernel(const int* __restrict__ src, const int* __restrict__ dst,
                            const float* __restrict__ w, int E) {
    int e = blockIdx.x * blockDim.x + threadIdx.x;
    if (e >= E) return;
    int s = src[e];
    int d = dst[e];
    float nm = g_dinv[s] * w[e] * g_dinv[d];
    int slot = g_rowptr[d] + atomicAdd(&g_fill[d], 1);
    g_epack[slot] = make_int2(s, __float_as_int(nm));
}

// ---------------------------------------------------------------------------
// GEMM: g_xw = act(in) @ W  (fp32). in == nullptr -> read g_h (layers 2,3).
// Block: 256 threads, 128 rows. Thread tile: 16 rows x 2 adjacent cols.
// In-place safe: block reads its 128 rows to SMEM before any write.
// ---------------------------------------------------------------------------
__global__ __launch_bounds__(256) void gemm_kernel(
    const float* in, const float* __restrict__ W,
    int n_rows, int relu_in)
{
    __shared__ float Ws[HH * HH];       // [k][c]
    __shared__ float Hs[128][HH];       // [r][k]

    const float* src_in = (in == nullptr) ? g_h : in;

    int tid = threadIdx.x;
    int row0 = blockIdx.x * 128;

    for (int i = tid; i < HH * HH; i += 256) Ws[i] = W[i];

    for (int i = tid; i < 128 * 16; i += 256) {
        int r = i >> 4;
        int c4 = i & 15;
        int grow = row0 + r;
        float4 v = make_float4(0.f, 0.f, 0.f, 0.f);
        if (grow < n_rows) v = ((const float4*)src_in)[grow * 16 + c4];
        if (relu_in) {
            v.x = fmaxf(v.x, 0.f); v.y = fmaxf(v.y, 0.f);
            v.z = fmaxf(v.z, 0.f); v.w = fmaxf(v.w, 0.f);
        }
        Hs[r][c4 * 4 + 0] = v.x;
        Hs[r][c4 * 4 + 1] = v.y;
        Hs[r][c4 * 4 + 2] = v.z;
        Hs[r][c4 * 4 + 3] = v.w;
    }
    __syncthreads();

    int tx = tid & 31;            // owns cols 2*tx, 2*tx+1
    int ty = tid >> 5;
    int rbase = ty * 16;

    float acc0[16];
    float acc1[16];
    #pragma unroll
    for (int r = 0; r < 16; r++) { acc0[r] = 0.f; acc1[r] = 0.f; }

    #pragma unroll 8
    for (int k = 0; k < HH; k++) {
        float2 w = ((const float2*)Ws)[k * 32 + tx];
        #pragma unroll
        for (int r = 0; r < 16; r++) {
            float hv = Hs[rbase + r][k];
            acc0[r] += hv * w.x;
            acc1[r] += hv * w.y;
        }
    }

    #pragma unroll
    for (int r = 0; r < 16; r++) {
        int grow = row0 + rbase + r;
        if (grow < n_rows) {
            float2 o; o.x = acc0[r]; o.y = acc1[r];
            ((float2*)g_xw)[grow * 32 + tx] = o;
        }
    }
}

// ---------------------------------------------------------------------------
// Pull aggregation (CSR): h[d] = b + selfc[d]*xw[d] + sum_e norm*xw[src].
// 16 lanes per dst (float4 each), 16 dsts per 256-thread block. NO atomics.
// Edge loop unrolled x2 for MLP (dual outstanding gathers).
// ---------------------------------------------------------------------------
__global__ __launch_bounds__(256) void agg_kernel(const float* __restrict__ b, int n)
{
    int d = blockIdx.x * 16 + (threadIdx.x >> 4);
    int lane = threadIdx.x & 15;
    if (d >= n) return;

    int e     = g_rowptr[d];
    int end   = g_rowptr[d + 1];

    float4 acc = make_float4(0.f, 0.f, 0.f, 0.f);
    float4 acc2 = make_float4(0.f, 0.f, 0.f, 0.f);
    const float4* xw4 = (const float4*)g_xw;

    for (; e + 2 <= end; e += 2) {
        int2 p0 = g_epack[e];
        int2 p1 = g_epack[e + 1];
        float4 v0 = xw4[p0.x * 16 + lane];
        float4 v1 = xw4[p1.x * 16 + lane];
        float n0 = __int_as_float(p0.y);
        float n1 = __int_as_float(p1.y);
        acc.x += n0 * v0.x;  acc.y += n0 * v0.y;
        acc.z += n0 * v0.z;  acc.w += n0 * v0.w;
        acc2.x += n1 * v1.x; acc2.y += n1 * v1.y;
        acc2.z += n1 * v1.z; acc2.w += n1 * v1.w;
    }
    if (e < end) {
        int2 p = g_epack[e];
        float nm = __int_as_float(p.y);
        float4 v = xw4[p.x * 16 + lane];
        acc.x += nm * v.x;
        acc.y += nm * v.y;
        acc.z += nm * v.z;
        acc.w += nm * v.w;
    }
    acc.x += acc2.x; acc.y += acc2.y; acc.z += acc2.z; acc.w += acc2.w;

    float sc = g_selfc[d];
    float4 sv = xw4[d * 16 + lane];
    float4 bv = ((const float4*)b)[lane];
    float4 o;
    o.x = bv.x + sc * sv.x + acc.x;
    o.y = bv.y + sc * sv.y + acc.y;
    o.z = bv.z + sc * sv.z + acc.z;
    o.w = bv.w + sc * sv.w + acc.w;
    ((float4*)g_h)[d * 16 + lane] = o;
}

// ---------------------------------------------------------------------------
// Pool: pooled[batch[i]] += g_h[i]; cnt[batch[i]] += 1
// ---------------------------------------------------------------------------
__global__ __launch_bounds__(256) void pool_kernel(
    const int* __restrict__ batch, int n)
{
    int t = blockIdx.x * blockDim.x + threadIdx.x;
    int i = t >> 4;
    if (i >= n) return;
    int lane = t & 15;
    int g = batch[i];
    float4 v = ((const float4*)g_h)[i * 16 + lane];
    float* p = g_pooled + g * HH + lane * 4;
    asm volatile("red.global.add.v4.f32 [%0], {%1, %2, %3, %4};"
                 :: "l"(p), "f"(v.x), "f"(v.y), "f"(v.z), "f"(v.w) : "memory");
    if (lane == 0) atomicAdd(&g_cnt[g], 1.0f);
}

// ---------------------------------------------------------------------------
// Head: out[g][c] = (pooled[g]/cnt[g]) @ Wl + bl
// ---------------------------------------------------------------------------
__global__ void final_kernel(const float* __restrict__ Wl, const float* __restrict__ bl,
                             float* __restrict__ out)
{
    int t = blockIdx.x * blockDim.x + threadIdx.x;
    if (t >= GG * CC) return;
    int g = t >> 1;
    int c = t & 1;
    float inv = 1.0f / fmaxf(g_cnt[g], 1.0f);
    float s = 0.0f;
    #pragma unroll
    for (int k = 0; k < HH; k++) s += g_pooled[g * HH + k] * Wl[k * CC + c];
    out[t] = s * inv + bl[c];
}

// ---------------------------------------------------------------------------
extern "C" void kernel_launch(void* const* d_in, const int* in_sizes, int n_in,
                              void* d_out, int out_size)
{
    const float* x     = (const float*)d_in[0];
    const int*   ei    = (const int*)d_in[1];     // [2, E]: src then dst
    const float* eattr = (const float*)d_in[2];
    const int*   batch = (const int*)d_in[3];
    const float* W1 = (const float*)d_in[4];
    const float* b1 = (const float*)d_in[5];
    const float* W2 = (const float*)d_in[6];
    const float* b2 = (const float*)d_in[7];
    const float* W3 = (const float*)d_in[8];
    const float* b3 = (const float*)d_in[9];
    const float* Wl = (const float*)d_in[10];
    const float* bl = (const float*)d_in[11];
    float* out = (float*)d_out;

    int N = in_sizes[0] / HH;
    int E = in_sizes[2];
    const int* src = ei;
    const int* dst = ei + E;

    int nb256 = (N + 255) / 256;      // also = scan segment count (<=512)
    int eb256 = (E + 255) / 256;
    int gemm_blocks = (N + 127) / 128;
    int agg_blocks  = (N + 15) / 16;
    int pool_blocks = (N * 16 + 255) / 256;

    // ---- Graph preprocessing (once per call; layer-invariant) ----
    init_kernel<<<nb256, 256>>>(N);
    histdeg_kernel<<<eb256, 256>>>(dst, eattr, E);
    dinv_kernel<<<nb256, 256>>>(N);
    scan_phase1<<<nb256, 256>>>(N);
    scan_phase2<<<1, 512>>>(nb256, N, E);
    scan_phase3<<<nb256, 256>>>(N);
    fill_kernel<<<eb256, 256>>>(src, dst, eattr, E);

    // ---- Layer 1 (input x) ----
    gemm_kernel<<<gemm_blocks, 256>>>(x, W1, N, 0);
    agg_kernel<<<agg_blocks, 256>>>(b1, N);

    // ---- Layer 2 (input g_h, relu fused into gemm load) ----
    gemm_kernel<<<gemm_blocks, 256>>>(nullptr, W2, N, 1);
    agg_kernel<<<agg_blocks, 256>>>(b2, N);

    // ---- Layer 3 ----
    gemm_kernel<<<gemm_blocks, 256>>>(nullptr, W3, N, 1);
    agg_kernel<<<agg_blocks, 256>>>(b3, N);

    // ---- Pool + head ----
    pool_kernel<<<pool_blocks, 256>>>(batch, N);
    final_kernel<<<(GG * CC + 255) / 256, 256>>>(Wl, bl, out);
}

// round 6
// speedup vs baseline: 1.4942x; 1.2083x over previous
#include <cuda_runtime.h>
#include <cuda_bf16.h>

// Problem constants (match reference)
#define NN 100000
#define EE 1000000
#define HH 64
#define GG 512
#define CC 2

// Scratch (no allocation allowed -> __device__ globals)
__device__ __nv_bfloat16 g_xwh[NN * HH];  // X @ W (bf16, gather side)
__device__ float g_h[NN * HH];            // hidden state (fp32)
__device__ float g_degw[NN];              // weighted degree
__device__ float g_dinv[NN];
__device__ float g_selfc[NN];             // 2 * dinv^2
__device__ int   g_hist[NN];              // in-degree (CSR sizes)
__device__ int   g_fill[NN];              // CSR fill cursors
__device__ int   g_rowptr[NN + 1];        // CSR row pointers
__device__ int   g_bsum[1024];            // block sums for scan
__device__ int   g_boff[1024];            // block offsets for scan
__device__ int2  g_epack[EE];             // {src, norm bits} sorted by dst
__device__ float g_pooled[GG * HH];
__device__ float g_cnt[GG];

// ---------------------------------------------------------------------------
__global__ void init_kernel(int n) {
    int t = blockIdx.x * blockDim.x + threadIdx.x;
    if (t < n) { g_degw[t] = 0.0f; g_hist[t] = 0; g_fill[t] = 0; }
    if (t < GG * HH) g_pooled[t] = 0.0f;
    if (t < GG) g_cnt[t] = 0.0f;
}

// deg[dst] += w ; hist[dst] += 1
__global__ void histdeg_kernel(const int* __restrict__ dst, const float* __restrict__ w, int E) {
    int e = blockIdx.x * blockDim.x + threadIdx.x;
    if (e < E) {
        int d = dst[e];
        atomicAdd(&g_degw[d], w[e]);
        atomicAdd(&g_hist[d], 1);
    }
}

// ---------------------------------------------------------------------------
// scan phase 1 (block sums) + fused dinv/selfc + fused graph-size count
// ---------------------------------------------------------------------------
__global__ void scan_phase1(const int* __restrict__ batch, int n) {
    __shared__ int s[256];
    int i = blockIdx.x * 256 + threadIdx.x;
    int v = 0;
    if (i < n) {
        v = g_hist[i];
        float di = rsqrtf(g_degw[i] + 2.0f);
        g_dinv[i] = di;
        g_selfc[i] = 2.0f * di * di;
        atomicAdd(&g_cnt[batch[i]], 1.0f);
    }
    s[threadIdx.x] = v;
    __syncthreads();
    for (int off = 128; off > 0; off >>= 1) {
        if (threadIdx.x < off) s[threadIdx.x] += s[threadIdx.x + off];
        __syncthreads();
    }
    if (threadIdx.x == 0) g_bsum[blockIdx.x] = s[0];
}

__global__ void scan_phase2(int nblocks, int n, int E) {  // scan of block sums
    __shared__ int s[512];
    int t = threadIdx.x;
    int v = (t < nblocks) ? g_bsum[t] : 0;
    s[t] = v;
    __syncthreads();
    for (int off = 1; off < 512; off <<= 1) {
        int add = (t >= off) ? s[t - off] : 0;
        __syncthreads();
        s[t] += add;
        __syncthreads();
    }
    if (t < nblocks) g_boff[t] = s[t] - v;     // exclusive
    if (t == 0) g_rowptr[n] = E;
}

__global__ void scan_phase3(int n) {            // local scan + offset
    __shared__ int s[256];
    int t = threadIdx.x;
    int i = blockIdx.x * 256 + t;
    int v = (i < n) ? g_hist[i] : 0;
    s[t] = v;
    __syncthreads();
    for (int off = 1; off < 256; off <<= 1) {
        int add = (t >= off) ? s[t - off] : 0;
        __syncthreads();
        s[t] += add;
        __syncthreads();
    }
    if (i < n) g_rowptr[i] = g_boff[blockIdx.x] + s[t] - v;  // exclusive
}

// ---------------------------------------------------------------------------
// CSR fill: slot = rowptr[dst] + fill[dst]++; epack[slot] = {src, norm}
// ---------------------------------------------------------------------------
__global__ void fill_kernel(const int* __restrict__ src, const int* __restrict__ dst,
                            const float* __restrict__ w, int E) {
    int e = blockIdx.x * blockDim.x + threadIdx.x;
    if (e >= E) return;
    int s = src[e];
    int d = dst[e];
    float nm = g_dinv[s] * w[e] * g_dinv[d];
    int slot = g_rowptr[d] + atomicAdd(&g_fill[d], 1);
    g_epack[slot] = make_int2(s, __float_as_int(nm));
}

// ---------------------------------------------------------------------------
// GEMM: g_xwh = bf16(act(in) @ W). fp32 accumulate, single bf16 round on store.
// in == nullptr -> read g_h (layers 2,3). In-place safe (reads before writes).
// ---------------------------------------------------------------------------
__global__ __launch_bounds__(256) void gemm_kernel(
    const float* in, const float* __restrict__ W,
    int n_rows, int relu_in)
{
    __shared__ float Ws[HH * HH];       // [k][c]
    __shared__ float Hs[128][HH];       // [r][k]

    const float* src_in = (in == nullptr) ? g_h : in;

    int tid = threadIdx.x;
    int row0 = blockIdx.x * 128;

    for (int i = tid; i < HH * HH; i += 256) Ws[i] = W[i];

    for (int i = tid; i < 128 * 16; i += 256) {
        int r = i >> 4;
        int c4 = i & 15;
        int grow = row0 + r;
        float4 v = make_float4(0.f, 0.f, 0.f, 0.f);
        if (grow < n_rows) v = ((const float4*)src_in)[grow * 16 + c4];
        if (relu_in) {
            v.x = fmaxf(v.x, 0.f); v.y = fmaxf(v.y, 0.f);
            v.z = fmaxf(v.z, 0.f); v.w = fmaxf(v.w, 0.f);
        }
        Hs[r][c4 * 4 + 0] = v.x;
        Hs[r][c4 * 4 + 1] = v.y;
        Hs[r][c4 * 4 + 2] = v.z;
        Hs[r][c4 * 4 + 3] = v.w;
    }
    __syncthreads();

    int tx = tid & 31;            // owns cols 2*tx, 2*tx+1
    int ty = tid >> 5;
    int rbase = ty * 16;

    float acc0[16];
    float acc1[16];
    #pragma unroll
    for (int r = 0; r < 16; r++) { acc0[r] = 0.f; acc1[r] = 0.f; }

    #pragma unroll 8
    for (int k = 0; k < HH; k++) {
        float2 w = ((const float2*)Ws)[k * 32 + tx];
        #pragma unroll
        for (int r = 0; r < 16; r++) {
            float hv = Hs[rbase + r][k];
            acc0[r] += hv * w.x;
            acc1[r] += hv * w.y;
        }
    }

    #pragma unroll
    for (int r = 0; r < 16; r++) {
        int grow = row0 + rbase + r;
        if (grow < n_rows) {
            ((__nv_bfloat162*)g_xwh)[grow * 32 + tx] =
                __floats2bfloat162_rn(acc0[r], acc1[r]);
        }
    }
}

// ---------------------------------------------------------------------------
// Pull aggregation (CSR): o[d] = b + selfc[d]*xw[d] + sum_e norm*xw[src].
// 8 lanes per dst; each lane handles 8 features (one uint4 of bf16 per edge).
// 32 dsts per 256-thread block. NO atomics in edge loop. Unrolled x2 for MLP.
// mode 0: write o to g_h. mode 1: red.add o into g_pooled[batch[d]] (layer 3).
// ---------------------------------------------------------------------------
__global__ __launch_bounds__(256) void agg_kernel(
    const float* __restrict__ b, const int* __restrict__ batch, int n, int mode)
{
    int d = blockIdx.x * 32 + (threadIdx.x >> 3);
    int lane = threadIdx.x & 7;
    if (d >= n) return;

    int e   = g_rowptr[d];
    int end = g_rowptr[d + 1];

    float4 a0 = make_float4(0.f, 0.f, 0.f, 0.f);
    float4 a1 = make_float4(0.f, 0.f, 0.f, 0.f);
    float4 c0 = make_float4(0.f, 0.f, 0.f, 0.f);
    float4 c1 = make_float4(0.f, 0.f, 0.f, 0.f);
    const uint4* xw4 = (const uint4*)g_xwh;   // 8 bf16 per uint4; 8 per row

    for (; e + 2 <= end; e += 2) {
        int2 p0 = g_epack[e];
        int2 p1 = g_epack[e + 1];
        uint4 r0 = xw4[p0.x * 8 + lane];
        uint4 r1 = xw4[p1.x * 8 + lane];
        float n0 = __int_as_float(p0.y);
        float n1 = __int_as_float(p1.y);
        float2 f;
        f = __bfloat1622float2(*(__nv_bfloat162*)&r0.x); a0.x += n0*f.x; a0.y += n0*f.y;
        f = __bfloat1622float2(*(__nv_bfloat162*)&r0.y); a0.z += n0*f.x; a0.w += n0*f.y;
        f = __bfloat1622float2(*(__nv_bfloat162*)&r0.z); a1.x += n0*f.x; a1.y += n0*f.y;
        f = __bfloat1622float2(*(__nv_bfloat162*)&r0.w); a1.z += n0*f.x; a1.w += n0*f.y;
        f = __bfloat1622float2(*(__nv_bfloat162*)&r1.x); c0.x += n1*f.x; c0.y += n1*f.y;
        f = __bfloat1622float2(*(__nv_bfloat162*)&r1.y); c0.z += n1*f.x; c0.w += n1*f.y;
        f = __bfloat1622float2(*(__nv_bfloat162*)&r1.z); c1.x += n1*f.x; c1.y += n1*f.y;
        f = __bfloat1622float2(*(__nv_bfloat162*)&r1.w); c1.z += n1*f.x; c1.w += n1*f.y;
    }
    if (e < end) {
        int2 p = g_epack[e];
        uint4 r0 = xw4[p.x * 8 + lane];
        float n0 = __int_as_float(p.y);
        float2 f;
        f = __bfloat1622float2(*(__nv_bfloat162*)&r0.x); a0.x += n0*f.x; a0.y += n0*f.y;
        f = __bfloat1622float2(*(__nv_bfloat162*)&r0.y); a0.z += n0*f.x; a0.w += n0*f.y;
        f = __bfloat1622float2(*(__nv_bfloat162*)&r0.z); a1.x += n0*f.x; a1.y += n0*f.y;
        f = __bfloat1622float2(*(__nv_bfloat162*)&r0.w); a1.z += n0*f.x; a1.w += n0*f.y;
    }
    a0.x += c0.x; a0.y += c0.y; a0.z += c0.z; a0.w += c0.w;
    a1.x += c1.x; a1.y += c1.y; a1.z += c1.z; a1.w += c1.w;

    // self-loop + bias
    float sc = g_selfc[d];
    uint4 rs = xw4[d * 8 + lane];
    float4 bv0 = ((const float4*)b)[lane * 2];
    float4 bv1 = ((const float4*)b)[lane * 2 + 1];
    float2 f;
    f = __bfloat1622float2(*(__nv_bfloat162*)&rs.x); a0.x += sc*f.x; a0.y += sc*f.y;
    f = __bfloat1622float2(*(__nv_bfloat162*)&rs.y); a0.z += sc*f.x; a0.w += sc*f.y;
    f = __bfloat1622float2(*(__nv_bfloat162*)&rs.z); a1.x += sc*f.x; a1.y += sc*f.y;
    f = __bfloat1622float2(*(__nv_bfloat162*)&rs.w); a1.z += sc*f.x; a1.w += sc*f.y;
    a0.x += bv0.x; a0.y += bv0.y; a0.z += bv0.z; a0.w += bv0.w;
    a1.x += bv1.x; a1.y += bv1.y; a1.z += bv1.z; a1.w += bv1.w;

    if (mode == 0) {
        ((float4*)g_h)[d * 16 + lane * 2]     = a0;
        ((float4*)g_h)[d * 16 + lane * 2 + 1] = a1;
    } else {
        // layer 3: accumulate straight into pooled sums
        float* p = g_pooled + batch[d] * HH + lane * 8;
        asm volatile("red.global.add.v4.f32 [%0], {%1, %2, %3, %4};"
                     :: "l"(p), "f"(a0.x), "f"(a0.y), "f"(a0.z), "f"(a0.w) : "memory");
        asm volatile("red.global.add.v4.f32 [%0], {%1, %2, %3, %4};"
                     :: "l"(p + 4), "f"(a1.x), "f"(a1.y), "f"(a1.z), "f"(a1.w) : "memory");
    }
}

// ---------------------------------------------------------------------------
// Head: out[g][c] = (pooled[g]/cnt[g]) @ Wl + bl
// ---------------------------------------------------------------------------
__global__ void final_kernel(const float* __restrict__ Wl, const float* __restrict__ bl,
                             float* __restrict__ out)
{
    int t = blockIdx.x * blockDim.x + threadIdx.x;
    if (t >= GG * CC) return;
    int g = t >> 1;
    int c = t & 1;
    float inv = 1.0f / fmaxf(g_cnt[g], 1.0f);
    float s = 0.0f;
    #pragma unroll
    for (int k = 0; k < HH; k++) s += g_pooled[g * HH + k] * Wl[k * CC + c];
    out[t] = s * inv + bl[c];
}

// ---------------------------------------------------------------------------
extern "C" void kernel_launch(void* const* d_in, const int* in_sizes, int n_in,
                              void* d_out, int out_size)
{
    const float* x     = (const float*)d_in[0];
    const int*   ei    = (const int*)d_in[1];     // [2, E]: src then dst
    const float* eattr = (const float*)d_in[2];
    const int*   batch = (const int*)d_in[3];
    const float* W1 = (const float*)d_in[4];
    const float* b1 = (const float*)d_in[5];
    const float* W2 = (const float*)d_in[6];
    const float* b2 = (const float*)d_in[7];
    const float* W3 = (const float*)d_in[8];
    const float* b3 = (const float*)d_in[9];
    const float* Wl = (const float*)d_in[10];
    const float* bl = (const float*)d_in[11];
    float* out = (float*)d_out;

    int N = in_sizes[0] / HH;
    int E = in_sizes[2];
    const int* src = ei;
    const int* dst = ei + E;

    int nb256 = (N + 255) / 256;      // scan segment count (<=512)
    int eb256 = (E + 255) / 256;
    int gemm_blocks = (N + 127) / 128;
    int agg_blocks  = (N + 31) / 32;

    // ---- Graph preprocessing (once per call; layer-invariant) ----
    init_kernel<<<nb256, 256>>>(N);
    histdeg_kernel<<<eb256, 256>>>(dst, eattr, E);
    scan_phase1<<<nb256, 256>>>(batch, N);    // + dinv/selfc + graph counts
    scan_phase2<<<1, 512>>>(nb256, N, E);
    scan_phase3<<<nb256, 256>>>(N);
    fill_kernel<<<eb256, 256>>>(src, dst, eattr, E);

    // ---- Layer 1 (input x) ----
    gemm_kernel<<<gemm_blocks, 256>>>(x, W1, N, 0);
    agg_kernel<<<agg_blocks, 256>>>(b1, batch, N, 0);

    // ---- Layer 2 (input g_h, relu fused into gemm load) ----
    gemm_kernel<<<gemm_blocks, 256>>>(nullptr, W2, N, 1);
    agg_kernel<<<agg_blocks, 256>>>(b2, batch, N, 0);

    // ---- Layer 3: aggregation fused with mean-pool accumulation ----
    gemm_kernel<<<gemm_blocks, 256>>>(nullptr, W3, N, 1);
    agg_kernel<<<agg_blocks, 256>>>(b3, batch, N, 1);

    // ---- Head ----
    final_kernel<<<(GG * CC + 255) / 256, 256>>>(Wl, bl, out);
}